// round 1
// baseline (speedup 1.0000x reference)
#include <cuda_runtime.h>
#include <cuda_bf16.h>

// Problem constants (fixed by the dataset)
#define NN 50000
#define NE 800000
#define KIN 256
#define HO 128            // HEADS*OUT
#define HEADS 4
#define OUTD 32
#define NEG_SLOPE 0.2f

// ---------------- device scratch (allocation-free workaround) ----------------
__device__ float g_feat[NN * HO];          // projected node features [N,128]
__device__ float g_el[NN * HEADS];
__device__ float g_er[NN * HEADS];
__device__ float g_logit[NE * HEADS];      // logits, then reused as expv
__device__ unsigned g_mx[NN * HEADS];      // encoded float max
__device__ float g_denom[NN * HEADS];
__device__ int g_cnt[NN];
__device__ int g_cursor[NN];
__device__ int g_rowptr[NN + 1];
__device__ int g_eids[NE];
__device__ float g_V[64 * HEADS];          // W_e folded with attn_e
__device__ int g_part[64];
__device__ int g_partx[64];

// monotone float<->uint encoding for atomicMax on floats
__device__ __forceinline__ unsigned fenc(float f) {
    unsigned b = __float_as_uint(f);
    return b ^ ((b >> 31) ? 0xFFFFFFFFu : 0x80000000u);
}
__device__ __forceinline__ float fdec(unsigned u) {
    unsigned b = u ^ ((u >> 31) ? 0x80000000u : 0xFFFFFFFFu);
    return __uint_as_float(b);
}
#define ENC_NEG_INF 0x007FFFFFu   // fenc(-inf)

// ---------------- init ----------------
__global__ void init_kernel() {
    int i = blockIdx.x * blockDim.x + threadIdx.x;
    if (i < NN * HEADS) { g_denom[i] = 0.f; g_mx[i] = ENC_NEG_INF; }
    if (i < NN) { g_cnt[i] = 0; g_cursor[i] = 0; }
}

// ---------------- fold W_e with attn_e: V[k][h] ----------------
__global__ void vprep_kernel(const float* __restrict__ We, const float* __restrict__ ae) {
    int t = threadIdx.x;            // 256 threads
    int k = t >> 2, h = t & 3;
    float acc = 0.f;
    #pragma unroll
    for (int d = 0; d < OUTD; d++)
        acc += We[k * HO + h * OUTD + d] * ae[h * OUTD + d];
    g_V[k * HEADS + h] = acc;
}

// ---------------- node GEMM: g_feat = node_feat @ W  (128x128x16 tiles) ----------------
__global__ void gemm_feat_kernel(const float* __restrict__ A, const float* __restrict__ B, int N) {
    __shared__ float As[16][128];
    __shared__ float Bs[16][128];
    int tid = threadIdx.x;          // 256 threads
    int tx = tid & 15, ty = tid >> 4;
    int rowBase = blockIdx.x * 128;
    float acc[8][8];
    #pragma unroll
    for (int i = 0; i < 8; i++)
        #pragma unroll
        for (int j = 0; j < 8; j++) acc[i][j] = 0.f;

    for (int k0 = 0; k0 < KIN; k0 += 16) {
        #pragma unroll
        for (int l = 0; l < 2; l++) {
            int f = tid + l * 256;
            int r = f >> 2, c4 = f & 3;
            int gr = rowBase + r;
            float4 v = (gr < N) ? *(const float4*)(A + (size_t)gr * KIN + k0 + c4 * 4)
                                : make_float4(0.f, 0.f, 0.f, 0.f);
            As[c4 * 4 + 0][r] = v.x; As[c4 * 4 + 1][r] = v.y;
            As[c4 * 4 + 2][r] = v.z; As[c4 * 4 + 3][r] = v.w;
        }
        #pragma unroll
        for (int l = 0; l < 2; l++) {
            int f = tid + l * 256;
            int kk = f >> 5, c4 = f & 31;
            *(float4*)&Bs[kk][c4 * 4] = *(const float4*)(B + (size_t)(k0 + kk) * HO + c4 * 4);
        }
        __syncthreads();
        #pragma unroll
        for (int k = 0; k < 16; k++) {
            float a[8], b[8];
            *(float4*)&a[0] = *(float4*)&As[k][ty * 8];
            *(float4*)&a[4] = *(float4*)&As[k][ty * 8 + 4];
            *(float4*)&b[0] = *(float4*)&Bs[k][tx * 8];
            *(float4*)&b[4] = *(float4*)&Bs[k][tx * 8 + 4];
            #pragma unroll
            for (int i = 0; i < 8; i++)
                #pragma unroll
                for (int j = 0; j < 8; j++)
                    acc[i][j] = fmaf(a[i], b[j], acc[i][j]);
        }
        __syncthreads();
    }
    #pragma unroll
    for (int i = 0; i < 8; i++) {
        int node = rowBase + ty * 8 + i;
        if (node < N) {
            float* o = g_feat + (size_t)node * HO + tx * 8;
            *(float4*)o       = make_float4(acc[i][0], acc[i][1], acc[i][2], acc[i][3]);
            *(float4*)(o + 4) = make_float4(acc[i][4], acc[i][5], acc[i][6], acc[i][7]);
        }
    }
}

// ---------------- el/er: warp per node ----------------
__global__ void eler_kernel(const float* __restrict__ al, const float* __restrict__ ar, int N) {
    int warp = (blockIdx.x * blockDim.x + threadIdx.x) >> 5;
    int lane = threadIdx.x & 31;
    if (warp >= N) return;
    int h = lane >> 3;
    int dsub = (lane & 7) * 4;
    float4 f = *(const float4*)(g_feat + (size_t)warp * HO + lane * 4);
    float4 a = *(const float4*)(al + h * OUTD + dsub);
    float4 b = *(const float4*)(ar + h * OUTD + dsub);
    float pl = f.x * a.x + f.y * a.y + f.z * a.z + f.w * a.w;
    float pr = f.x * b.x + f.y * b.y + f.z * b.z + f.w * b.w;
    #pragma unroll
    for (int off = 4; off >= 1; off >>= 1) {
        pl += __shfl_down_sync(0xffffffffu, pl, off, 8);
        pr += __shfl_down_sync(0xffffffffu, pr, off, 8);
    }
    if ((lane & 7) == 0) {
        g_el[warp * HEADS + h] = pl;
        g_er[warp * HEADS + h] = pr;
    }
}

// ---------------- edge logits + segment max + dst histogram ----------------
// 8 lanes per edge, 4 edges per warp
__global__ void edge_logits_kernel(const float* __restrict__ ef,
                                   const int* __restrict__ src,
                                   const int* __restrict__ dst, int E) {
    __shared__ float Vs[64 * HEADS];
    if (threadIdx.x < 256) Vs[threadIdx.x] = g_V[threadIdx.x];
    __syncthreads();

    int warp = (blockIdx.x * blockDim.x + threadIdx.x) >> 5;
    int lane = threadIdx.x & 31;
    int grp = lane >> 3;
    int r = lane & 7;
    int e = warp * 4 + grp;
    if (e >= E) return;

    const float4* p = (const float4*)(ef + (size_t)e * 64 + r * 8);
    float4 x0 = p[0], x1 = p[1];
    float v[8] = {x0.x, x0.y, x0.z, x0.w, x1.x, x1.y, x1.z, x1.w};
    float acc[HEADS] = {0.f, 0.f, 0.f, 0.f};
    int base = r * 8;
    #pragma unroll
    for (int i = 0; i < 8; i++)
        #pragma unroll
        for (int h = 0; h < HEADS; h++)
            acc[h] = fmaf(v[i], Vs[(base + i) * HEADS + h], acc[h]);
    #pragma unroll
    for (int off = 4; off >= 1; off >>= 1)
        #pragma unroll
        for (int h = 0; h < HEADS; h++)
            acc[h] += __shfl_down_sync(0xffffffffu, acc[h], off, 8);

    if (r == 0) {
        int s = src[e], d = dst[e];
        float4 el4 = *(const float4*)(g_el + s * HEADS);
        float4 er4 = *(const float4*)(g_er + d * HEADS);
        float l[HEADS];
        l[0] = acc[0] + el4.x + er4.x;
        l[1] = acc[1] + el4.y + er4.y;
        l[2] = acc[2] + el4.z + er4.z;
        l[3] = acc[3] + el4.w + er4.w;
        #pragma unroll
        for (int h = 0; h < HEADS; h++)
            l[h] = (l[h] >= 0.f) ? l[h] : NEG_SLOPE * l[h];
        *(float4*)(g_logit + (size_t)e * HEADS) = make_float4(l[0], l[1], l[2], l[3]);
        #pragma unroll
        for (int h = 0; h < HEADS; h++)
            atomicMax(&g_mx[d * HEADS + h], fenc(l[h]));
        atomicAdd(&g_cnt[d], 1);
    }
}

// ---------------- 2-level exclusive scan of g_cnt -> g_rowptr ----------------
__global__ void scan1_kernel(int n) {
    __shared__ int s[1024];
    int tid = threadIdx.x;
    int i = blockIdx.x * 1024 + tid;
    int v = (i < n) ? g_cnt[i] : 0;
    s[tid] = v;
    __syncthreads();
    #pragma unroll
    for (int off = 1; off < 1024; off <<= 1) {
        int t = (tid >= off) ? s[tid - off] : 0;
        __syncthreads();
        s[tid] += t;
        __syncthreads();
    }
    if (i < n) g_rowptr[i] = s[tid] - v;   // exclusive within block
    if (tid == 1023) g_part[blockIdx.x] = s[1023];
}
__global__ void scan2_kernel(int nblocks) {
    __shared__ int s[64];
    int tid = threadIdx.x;   // 64 threads
    int v = (tid < nblocks) ? g_part[tid] : 0;
    s[tid] = v;
    __syncthreads();
    #pragma unroll
    for (int off = 1; off < 64; off <<= 1) {
        int t = (tid >= off) ? s[tid - off] : 0;
        __syncthreads();
        s[tid] += t;
        __syncthreads();
    }
    g_partx[tid] = s[tid] - v;  // exclusive
}
__global__ void scan3_kernel(int n, int E) {
    int i = blockIdx.x * blockDim.x + threadIdx.x;
    if (i < n) g_rowptr[i] += g_partx[i >> 10];
    if (i == 0) g_rowptr[n] = E;
}

// ---------------- expv + denom + CSR scatter ----------------
__global__ void expv_scatter_kernel(const int* __restrict__ dst, int E) {
    int e = blockIdx.x * blockDim.x + threadIdx.x;
    if (e >= E) return;
    int d = dst[e];
    float4 lg = *(const float4*)(g_logit + (size_t)e * HEADS);
    const unsigned* mp = &g_mx[d * HEADS];
    float4 ev;
    ev.x = expf(lg.x - fdec(mp[0]));
    ev.y = expf(lg.y - fdec(mp[1]));
    ev.z = expf(lg.z - fdec(mp[2]));
    ev.w = expf(lg.w - fdec(mp[3]));
    *(float4*)(g_logit + (size_t)e * HEADS) = ev;
    atomicAdd(&g_denom[d * HEADS + 0], ev.x);
    atomicAdd(&g_denom[d * HEADS + 1], ev.y);
    atomicAdd(&g_denom[d * HEADS + 2], ev.z);
    atomicAdd(&g_denom[d * HEADS + 3], ev.w);
    int pos = g_rowptr[d] + atomicAdd(&g_cursor[d], 1);
    g_eids[pos] = e;
}

// ---------------- aggregation: warp per dst node, no atomics ----------------
__global__ void aggregate_kernel(const int* __restrict__ src, float* __restrict__ out, int N) {
    int warp = (blockIdx.x * blockDim.x + threadIdx.x) >> 5;
    int lane = threadIdx.x & 31;
    if (warp >= N) return;
    int h = lane >> 3;
    int beg = g_rowptr[warp], end = g_rowptr[warp + 1];
    float4 acc = make_float4(0.f, 0.f, 0.f, 0.f);
    for (int j = beg; j < end; j++) {
        int e = g_eids[j];
        int s = src[e];
        float a = g_logit[(size_t)e * HEADS + h];       // expv
        float4 f = *(const float4*)(g_feat + (size_t)s * HO + lane * 4);
        acc.x = fmaf(a, f.x, acc.x);
        acc.y = fmaf(a, f.y, acc.y);
        acc.z = fmaf(a, f.z, acc.z);
        acc.w = fmaf(a, f.w, acc.w);
    }
    float4 res = make_float4(0.f, 0.f, 0.f, 0.f);
    if (end > beg) {
        float inv = 1.f / g_denom[warp * HEADS + h];
        res.x = fmaxf(acc.x * inv, 0.f);
        res.y = fmaxf(acc.y * inv, 0.f);
        res.z = fmaxf(acc.z * inv, 0.f);
        res.w = fmaxf(acc.w * inv, 0.f);
    }
    *(float4*)(out + (size_t)warp * HO + lane * 4) = res;
}

// ---------------- launch ----------------
extern "C" void kernel_launch(void* const* d_in, const int* in_sizes, int n_in,
                              void* d_out, int out_size) {
    const float* node_feat = (const float*)d_in[0];
    const float* edge_feat = (const float*)d_in[1];
    const float* W         = (const float*)d_in[2];
    const float* W_e       = (const float*)d_in[3];
    const float* attn_l    = (const float*)d_in[4];
    const float* attn_r    = (const float*)d_in[5];
    const float* attn_e    = (const float*)d_in[6];
    const int*   src       = (const int*)d_in[7];
    const int*   dst       = (const int*)d_in[8];
    float* out = (float*)d_out;

    int N = in_sizes[0] / KIN;
    int E = in_sizes[7];

    init_kernel<<<(N * HEADS + 255) / 256, 256>>>();
    vprep_kernel<<<1, 256>>>(W_e, attn_e);
    gemm_feat_kernel<<<(N + 127) / 128, 256>>>(node_feat, W, N);
    eler_kernel<<<(N + 7) / 8, 256>>>(attn_l, attn_r, N);
    edge_logits_kernel<<<((E + 3) / 4 + 7) / 8, 256>>>(edge_feat, src, dst, E);
    int nScanBlocks = (N + 1023) / 1024;
    scan1_kernel<<<nScanBlocks, 1024>>>(N);
    scan2_kernel<<<1, 64>>>(nScanBlocks);
    scan3_kernel<<<(N + 255) / 256, 256>>>(N, E);
    expv_scatter_kernel<<<(E + 255) / 256, 256>>>(dst, E);
    aggregate_kernel<<<(N + 7) / 8, 256>>>(src, out, N);
}

// round 3
// speedup vs baseline: 1.1139x; 1.1139x over previous
#include <cuda_runtime.h>
#include <cuda.h>
#include <cstdint>

#define NN 50000
#define NE 800000
#define KIN 256
#define HO 128            // HEADS*OUT
#define HEADS 4
#define OUTD 32
#define NEG_SLOPE 0.2f

// ---------------- device scratch ----------------
__device__ float g_feat[NN * HO];
__device__ float g_el[NN * HEADS];
__device__ float g_er[NN * HEADS];
__device__ float g_logit[NE * HEADS];
__device__ unsigned g_mx[NN * HEADS];
__device__ int g_cnt[NN];
__device__ int g_cursor[NN];
__device__ int g_rowptr[NN + 1];
__device__ int g_esrc[NE];         // CSR-ordered src ids
__device__ float4 g_eexp[NE];      // CSR-ordered exp(logit-max) per head
__device__ float g_V[64 * HEADS];
__device__ int g_part[64];
__device__ int g_partx[64];

// ---------------- helpers ----------------
__device__ __forceinline__ float tf32_rna(float x) {
    uint32_t u;
    asm("cvt.rna.tf32.f32 %0, %1;" : "=r"(u) : "f"(x));
    return __uint_as_float(u);
}
__device__ __forceinline__ void mma_tf32(float& d0, float& d1, float& d2, float& d3,
                                         uint32_t a0, uint32_t a1, uint32_t a2, uint32_t a3,
                                         uint32_t b0, uint32_t b1) {
    asm volatile(
        "mma.sync.aligned.m16n8k8.row.col.f32.tf32.tf32.f32 "
        "{%0,%1,%2,%3}, {%4,%5,%6,%7}, {%8,%9}, {%0,%1,%2,%3};"
        : "+f"(d0), "+f"(d1), "+f"(d2), "+f"(d3)
        : "r"(a0), "r"(a1), "r"(a2), "r"(a3), "r"(b0), "r"(b1));
}

// float<->uint monotone encoding for atomicMax on floats
__device__ __forceinline__ unsigned fenc(float f) {
    unsigned b = __float_as_uint(f);
    return b ^ ((b >> 31) ? 0xFFFFFFFFu : 0x80000000u);
}
__device__ __forceinline__ float fdec(unsigned u) {
    unsigned b = u ^ ((u >> 31) ? 0x80000000u : 0xFFFFFFFFu);
    return __uint_as_float(b);
}
#define ENC_NEG_INF 0x007FFFFFu

// ---------------- init ----------------
__global__ void init_kernel() {
    int i = blockIdx.x * blockDim.x + threadIdx.x;
    if (i < NN * HEADS) g_mx[i] = ENC_NEG_INF;
    if (i < NN) { g_cnt[i] = 0; g_cursor[i] = 0; }
}

// ---------------- fold W_e with attn_e ----------------
__global__ void vprep_kernel(const float* __restrict__ We, const float* __restrict__ ae) {
    int t = threadIdx.x;
    int k = t >> 2, h = t & 3;
    float acc = 0.f;
    #pragma unroll
    for (int d = 0; d < OUTD; d++)
        acc += We[k * HO + h * OUTD + d] * ae[h * OUTD + d];
    g_V[k * HEADS + h] = acc;
}

// ---------------- mma.sync tf32 GEMM (3xTF32) + fused el/er ----------------
// Block tile: M=64, N=128, 256 threads = 8 warps (warp_m = wid&1, warp_n = wid>>1)
// Warp tile: 32x32. Fragments per warp: 2 m-tiles x 4 n-tiles of m16n8k8.
#define A_STRIDE 36
#define B_STRIDE 136
#define AS_HI 0
#define AS_LO (64 * A_STRIDE)
#define BS_HI (2 * 64 * A_STRIDE)
#define BS_LO (2 * 64 * A_STRIDE + 32 * B_STRIDE)
#define GEMM_SMEM ((2 * 64 * A_STRIDE + 2 * 32 * B_STRIDE) * 4)

__global__ void __launch_bounds__(256, 2) gemm_mma_kernel(
    const float* __restrict__ A, const float* __restrict__ Bm,
    const float* __restrict__ al, const float* __restrict__ ar, int nRows) {
    extern __shared__ float sm[];
    int tid = threadIdx.x;
    int wid = tid >> 5;
    int lane = tid & 31;
    int gid = lane >> 2;      // 0..7
    int tig = lane & 3;       // 0..3
    int warp_m = wid & 1;     // 0..1 (32 rows each)
    int warp_n = wid >> 1;    // 0..3 (32 cols each == one head)
    int rowBase = blockIdx.x * 64;

    float c[2][4][4];
    #pragma unroll
    for (int mt = 0; mt < 2; mt++)
        #pragma unroll
        for (int nt = 0; nt < 4; nt++)
            #pragma unroll
            for (int j = 0; j < 4; j++) c[mt][nt][j] = 0.f;

    for (int ch = 0; ch < 8; ch++) {
        int k0 = ch * 32;
        __syncthreads();
        // Load A chunk [64 rows x 32 k], hi/lo split
        #pragma unroll
        for (int i = 0; i < 2; i++) {
            int f = i * 256 + tid;         // 512 float4 slots
            int r = f >> 3, kq = f & 7;
            int gr = rowBase + r;
            float4 v = make_float4(0.f, 0.f, 0.f, 0.f);
            if (gr < nRows) v = *(const float4*)(A + (size_t)gr * KIN + k0 + kq * 4);
            float* ph = sm + AS_HI + r * A_STRIDE + kq * 4;
            float* pl = sm + AS_LO + r * A_STRIDE + kq * 4;
            float h0 = tf32_rna(v.x), h1 = tf32_rna(v.y), h2 = tf32_rna(v.z), h3 = tf32_rna(v.w);
            ph[0] = h0; ph[1] = h1; ph[2] = h2; ph[3] = h3;
            pl[0] = tf32_rna(v.x - h0); pl[1] = tf32_rna(v.y - h1);
            pl[2] = tf32_rna(v.z - h2); pl[3] = tf32_rna(v.w - h3);
        }
        // Load B chunk [32 k x 128 n], hi/lo split
        #pragma unroll
        for (int i = 0; i < 4; i++) {
            int f = i * 256 + tid;         // 1024 float4 slots
            int r = f >> 5, cq = f & 31;
            float4 v = *(const float4*)(Bm + (size_t)(k0 + r) * HO + cq * 4);
            float* ph = sm + BS_HI + r * B_STRIDE + cq * 4;
            float* pl = sm + BS_LO + r * B_STRIDE + cq * 4;
            float h0 = tf32_rna(v.x), h1 = tf32_rna(v.y), h2 = tf32_rna(v.z), h3 = tf32_rna(v.w);
            ph[0] = h0; ph[1] = h1; ph[2] = h2; ph[3] = h3;
            pl[0] = tf32_rna(v.x - h0); pl[1] = tf32_rna(v.y - h1);
            pl[2] = tf32_rna(v.z - h2); pl[3] = tf32_rna(v.w - h3);
        }
        __syncthreads();

        #pragma unroll
        for (int ks = 0; ks < 4; ks++) {
            int kb = ks * 8;
            uint32_t ah[2][4], alo[2][4], bh[4][2], blo[4][2];
            #pragma unroll
            for (int mt = 0; mt < 2; mt++) {
                int ra = warp_m * 32 + mt * 16 + gid;
                const float* ph = sm + AS_HI + ra * A_STRIDE + kb + tig;
                const float* pl = sm + AS_LO + ra * A_STRIDE + kb + tig;
                ah[mt][0] = __float_as_uint(ph[0]);
                ah[mt][1] = __float_as_uint(ph[8 * A_STRIDE]);
                ah[mt][2] = __float_as_uint(ph[4]);
                ah[mt][3] = __float_as_uint(ph[8 * A_STRIDE + 4]);
                alo[mt][0] = __float_as_uint(pl[0]);
                alo[mt][1] = __float_as_uint(pl[8 * A_STRIDE]);
                alo[mt][2] = __float_as_uint(pl[4]);
                alo[mt][3] = __float_as_uint(pl[8 * A_STRIDE + 4]);
            }
            #pragma unroll
            for (int nt = 0; nt < 4; nt++) {
                int cb = warp_n * 32 + nt * 8 + gid;
                const float* ph = sm + BS_HI + (kb + tig) * B_STRIDE + cb;
                const float* pl = sm + BS_LO + (kb + tig) * B_STRIDE + cb;
                bh[nt][0] = __float_as_uint(ph[0]);
                bh[nt][1] = __float_as_uint(ph[4 * B_STRIDE]);
                blo[nt][0] = __float_as_uint(pl[0]);
                blo[nt][1] = __float_as_uint(pl[4 * B_STRIDE]);
            }
            #pragma unroll
            for (int mt = 0; mt < 2; mt++)
                #pragma unroll
                for (int nt = 0; nt < 4; nt++) {
                    mma_tf32(c[mt][nt][0], c[mt][nt][1], c[mt][nt][2], c[mt][nt][3],
                             ah[mt][0], ah[mt][1], ah[mt][2], ah[mt][3], bh[nt][0], bh[nt][1]);
                    mma_tf32(c[mt][nt][0], c[mt][nt][1], c[mt][nt][2], c[mt][nt][3],
                             alo[mt][0], alo[mt][1], alo[mt][2], alo[mt][3], bh[nt][0], bh[nt][1]);
                    mma_tf32(c[mt][nt][0], c[mt][nt][1], c[mt][nt][2], c[mt][nt][3],
                             ah[mt][0], ah[mt][1], ah[mt][2], ah[mt][3], blo[nt][0], blo[nt][1]);
                }
        }
    }

    // Epilogue: store feat + fused el/er.
    // C layout: c0/c1 -> (row=gid, col=2*tig / 2*tig+1), c2/c3 -> (row=gid+8, same cols)
    float alv[4][2], arv[4][2];
    #pragma unroll
    for (int nt = 0; nt < 4; nt++) {
        int col = warp_n * 32 + nt * 8 + 2 * tig;
        alv[nt][0] = al[col]; alv[nt][1] = al[col + 1];
        arv[nt][0] = ar[col]; arv[nt][1] = ar[col + 1];
    }
    #pragma unroll
    for (int mt = 0; mt < 2; mt++) {
        #pragma unroll
        for (int half = 0; half < 2; half++) {      // half=0: rows gid, half=1: rows gid+8
            int row = warp_m * 32 + mt * 16 + gid + half * 8;
            int node = rowBase + row;
            bool ok = (node < nRows);
            float el = 0.f, er = 0.f;
            #pragma unroll
            for (int nt = 0; nt < 4; nt++) {
                float v0 = c[mt][nt][half * 2 + 0];
                float v1 = c[mt][nt][half * 2 + 1];
                if (ok) {
                    int col = warp_n * 32 + nt * 8 + 2 * tig;
                    *(float2*)(g_feat + (size_t)node * HO + col) = make_float2(v0, v1);
                }
                el = fmaf(v0, alv[nt][0], el); el = fmaf(v1, alv[nt][1], el);
                er = fmaf(v0, arv[nt][0], er); er = fmaf(v1, arv[nt][1], er);
            }
            // reduce across the 4 lanes sharing this row (tig 0..3)
            el += __shfl_down_sync(0xffffffffu, el, 2, 4);
            el += __shfl_down_sync(0xffffffffu, el, 1, 4);
            er += __shfl_down_sync(0xffffffffu, er, 2, 4);
            er += __shfl_down_sync(0xffffffffu, er, 1, 4);
            if (ok && tig == 0) {
                g_el[node * HEADS + warp_n] = el;
                g_er[node * HEADS + warp_n] = er;
            }
        }
    }
}

// ---------------- edge logits + segment max + dst histogram ----------------
__global__ void edge_logits_kernel(const float* __restrict__ ef,
                                   const int* __restrict__ src,
                                   const int* __restrict__ dst, int E) {
    __shared__ float Vs[64 * HEADS];
    if (threadIdx.x < 256) Vs[threadIdx.x] = g_V[threadIdx.x];
    __syncthreads();

    int warp = (blockIdx.x * blockDim.x + threadIdx.x) >> 5;
    int lane = threadIdx.x & 31;
    int grp = lane >> 3;
    int r = lane & 7;
    int e = warp * 4 + grp;
    if (e >= E) return;

    const float4* p = (const float4*)(ef + (size_t)e * 64 + r * 8);
    float4 x0 = p[0], x1 = p[1];
    float v[8] = {x0.x, x0.y, x0.z, x0.w, x1.x, x1.y, x1.z, x1.w};
    float acc[HEADS] = {0.f, 0.f, 0.f, 0.f};
    int base = r * 8;
    #pragma unroll
    for (int i = 0; i < 8; i++)
        #pragma unroll
        for (int h = 0; h < HEADS; h++)
            acc[h] = fmaf(v[i], Vs[(base + i) * HEADS + h], acc[h]);
    #pragma unroll
    for (int off = 4; off >= 1; off >>= 1)
        #pragma unroll
        for (int h = 0; h < HEADS; h++)
            acc[h] += __shfl_down_sync(0xffffffffu, acc[h], off, 8);

    if (r == 0) {
        int s = src[e], d = dst[e];
        float4 el4 = *(const float4*)(g_el + s * HEADS);
        float4 er4 = *(const float4*)(g_er + d * HEADS);
        float l[HEADS];
        l[0] = acc[0] + el4.x + er4.x;
        l[1] = acc[1] + el4.y + er4.y;
        l[2] = acc[2] + el4.z + er4.z;
        l[3] = acc[3] + el4.w + er4.w;
        #pragma unroll
        for (int h = 0; h < HEADS; h++)
            l[h] = (l[h] >= 0.f) ? l[h] : NEG_SLOPE * l[h];
        *(float4*)(g_logit + (size_t)e * HEADS) = make_float4(l[0], l[1], l[2], l[3]);
        #pragma unroll
        for (int h = 0; h < HEADS; h++)
            atomicMax(&g_mx[d * HEADS + h], fenc(l[h]));
        atomicAdd(&g_cnt[d], 1);
    }
}

// ---------------- scans ----------------
__global__ void scan1_kernel(int n) {
    __shared__ int s[1024];
    int tid = threadIdx.x;
    int i = blockIdx.x * 1024 + tid;
    int v = (i < n) ? g_cnt[i] : 0;
    s[tid] = v;
    __syncthreads();
    #pragma unroll
    for (int off = 1; off < 1024; off <<= 1) {
        int t = (tid >= off) ? s[tid - off] : 0;
        __syncthreads();
        s[tid] += t;
        __syncthreads();
    }
    if (i < n) g_rowptr[i] = s[tid] - v;
    if (tid == 1023) g_part[blockIdx.x] = s[1023];
}
__global__ void scan2_kernel(int nblocks) {
    __shared__ int s[64];
    int tid = threadIdx.x;
    int v = (tid < nblocks) ? g_part[tid] : 0;
    s[tid] = v;
    __syncthreads();
    #pragma unroll
    for (int off = 1; off < 64; off <<= 1) {
        int t = (tid >= off) ? s[tid - off] : 0;
        __syncthreads();
        s[tid] += t;
        __syncthreads();
    }
    g_partx[tid] = s[tid] - v;
}
__global__ void scan3_kernel(int n, int E) {
    int i = blockIdx.x * blockDim.x + threadIdx.x;
    if (i < n) g_rowptr[i] += g_partx[i >> 10];
    if (i == 0) g_rowptr[n] = E;
}

// ---------------- scatter: build packed CSR (src, exp4) ----------------
__global__ void scatter_kernel(const int* __restrict__ src, const int* __restrict__ dst, int E) {
    int e = blockIdx.x * blockDim.x + threadIdx.x;
    if (e >= E) return;
    int d = dst[e];
    float4 lg = *(const float4*)(g_logit + (size_t)e * HEADS);
    const unsigned* mp = &g_mx[d * HEADS];
    float4 ev;
    ev.x = expf(lg.x - fdec(mp[0]));
    ev.y = expf(lg.y - fdec(mp[1]));
    ev.z = expf(lg.z - fdec(mp[2]));
    ev.w = expf(lg.w - fdec(mp[3]));
    int pos = g_rowptr[d] + atomicAdd(&g_cursor[d], 1);
    g_esrc[pos] = src[e];
    g_eexp[pos] = ev;
}

// ---------------- aggregation: warp per dst node, denom inline ----------------
__global__ void aggregate_kernel(float* __restrict__ out, int N) {
    int warp = (blockIdx.x * blockDim.x + threadIdx.x) >> 5;
    int lane = threadIdx.x & 31;
    if (warp >= N) return;
    int h = lane >> 3;
    int beg = g_rowptr[warp], end = g_rowptr[warp + 1];
    const float* ge = (const float*)g_eexp;
    float denom = 0.f;
    float4 acc = make_float4(0.f, 0.f, 0.f, 0.f);
    int s_next = 0;
    float a_next = 0.f;
    if (beg < end) { s_next = g_esrc[beg]; a_next = ge[(size_t)beg * 4 + h]; }
    for (int j = beg; j < end; j++) {
        int s = s_next;
        float a = a_next;
        if (j + 1 < end) { s_next = g_esrc[j + 1]; a_next = ge[(size_t)(j + 1) * 4 + h]; }
        float4 f = *(const float4*)(g_feat + (size_t)s * HO + lane * 4);
        acc.x = fmaf(a, f.x, acc.x);
        acc.y = fmaf(a, f.y, acc.y);
        acc.z = fmaf(a, f.z, acc.z);
        acc.w = fmaf(a, f.w, acc.w);
        denom += a;
    }
    float4 res = make_float4(0.f, 0.f, 0.f, 0.f);
    if (end > beg) {
        float inv = 1.f / denom;
        res.x = fmaxf(acc.x * inv, 0.f);
        res.y = fmaxf(acc.y * inv, 0.f);
        res.z = fmaxf(acc.z * inv, 0.f);
        res.w = fmaxf(acc.w * inv, 0.f);
    }
    *(float4*)(out + (size_t)warp * HO + lane * 4) = res;
}

// ---------------- launch ----------------
extern "C" void kernel_launch(void* const* d_in, const int* in_sizes, int n_in,
                              void* d_out, int out_size) {
    const float* node_feat = (const float*)d_in[0];
    const float* edge_feat = (const float*)d_in[1];
    const float* W         = (const float*)d_in[2];
    const float* W_e       = (const float*)d_in[3];
    const float* attn_l    = (const float*)d_in[4];
    const float* attn_r    = (const float*)d_in[5];
    const float* attn_e    = (const float*)d_in[6];
    const int*   src       = (const int*)d_in[7];
    const int*   dst       = (const int*)d_in[8];
    float* out = (float*)d_out;

    int N = in_sizes[0] / KIN;
    int E = in_sizes[7];

    cudaFuncSetAttribute(gemm_mma_kernel,
                         cudaFuncAttributeMaxDynamicSharedMemorySize, GEMM_SMEM);

    init_kernel<<<(N * HEADS + 255) / 256, 256>>>();
    vprep_kernel<<<1, 256>>>(W_e, attn_e);
    gemm_mma_kernel<<<(N + 63) / 64, 256, GEMM_SMEM>>>(node_feat, W, attn_l, attn_r, N);
    edge_logits_kernel<<<((E + 3) / 4 + 7) / 8, 256>>>(edge_feat, src, dst, E);
    int nScanBlocks = (N + 1023) / 1024;
    scan1_kernel<<<nScanBlocks, 1024>>>(N);
    scan2_kernel<<<1, 64>>>(nScanBlocks);
    scan3_kernel<<<(N + 255) / 256, 256>>>(N, E);
    scatter_kernel<<<(E + 255) / 256, 256>>>(src, dst, E);
    aggregate_kernel<<<(N + 7) / 8, 256>>>(out, N);
}

// round 4
// speedup vs baseline: 1.8164x; 1.6306x over previous
#include <cuda_runtime.h>
#include <cuda.h>
#include <cstdint>

#define NN 50000
#define NE 800000
#define KIN 256
#define HO 128            // HEADS*OUT
#define HEADS 4
#define OUTD 32
#define NEG_SLOPE 0.2f

// ---------------- device scratch ----------------
__device__ float g_feat[NN * HO];
__device__ float g_el[NN * HEADS];
__device__ float g_er[NN * HEADS];
__device__ float g_logit[NE * HEADS];
__device__ unsigned g_mx[NN * HEADS];
__device__ int g_cnt[NN];
__device__ int g_cursor[NN];
__device__ int g_rowptr[NN + 1];
__device__ int g_esrc[NE];         // CSR-ordered src ids
__device__ float4 g_eexp[NE];      // CSR-ordered exp(logit-max) per head
__device__ float g_V[64 * HEADS];
__device__ int g_part[64];
__device__ int g_partx[64];

// ---------------- helpers ----------------
__device__ __forceinline__ float tf32_rna(float x) {
    uint32_t u;
    asm("cvt.rna.tf32.f32 %0, %1;" : "=r"(u) : "f"(x));
    return __uint_as_float(u);
}
__device__ __forceinline__ void mma_tf32(float& d0, float& d1, float& d2, float& d3,
                                         uint32_t a0, uint32_t a1, uint32_t a2, uint32_t a3,
                                         uint32_t b0, uint32_t b1) {
    asm volatile(
        "mma.sync.aligned.m16n8k8.row.col.f32.tf32.tf32.f32 "
        "{%0,%1,%2,%3}, {%4,%5,%6,%7}, {%8,%9}, {%0,%1,%2,%3};"
        : "+f"(d0), "+f"(d1), "+f"(d2), "+f"(d3)
        : "r"(a0), "r"(a1), "r"(a2), "r"(a3), "r"(b0), "r"(b1));
}

// float<->uint monotone encoding for atomicMax on floats
__device__ __forceinline__ unsigned fenc(float f) {
    unsigned b = __float_as_uint(f);
    return b ^ ((b >> 31) ? 0xFFFFFFFFu : 0x80000000u);
}
__device__ __forceinline__ float fdec(unsigned u) {
    unsigned b = u ^ ((u >> 31) ? 0x80000000u : 0xFFFFFFFFu);
    return __uint_as_float(b);
}
#define ENC_NEG_INF 0x007FFFFFu

// ---------------- init ----------------
__global__ void init_kernel() {
    int i = blockIdx.x * blockDim.x + threadIdx.x;
    if (i < NN * HEADS) g_mx[i] = ENC_NEG_INF;
    if (i < NN) { g_cnt[i] = 0; g_cursor[i] = 0; }
}

// ---------------- fold W_e with attn_e ----------------
__global__ void vprep_kernel(const float* __restrict__ We, const float* __restrict__ ae) {
    int t = threadIdx.x;
    int k = t >> 2, h = t & 3;
    float acc = 0.f;
    #pragma unroll
    for (int d = 0; d < OUTD; d++)
        acc += We[k * HO + h * OUTD + d] * ae[h * OUTD + d];
    g_V[k * HEADS + h] = acc;
}

// ---------------- mma.sync tf32 GEMM (3xTF32) + fused el/er ----------------
#define A_STRIDE 36
#define B_STRIDE 136
#define AS_HI 0
#define AS_LO (64 * A_STRIDE)
#define BS_HI (2 * 64 * A_STRIDE)
#define BS_LO (2 * 64 * A_STRIDE + 32 * B_STRIDE)
#define GEMM_SMEM ((2 * 64 * A_STRIDE + 2 * 32 * B_STRIDE) * 4)

__global__ void __launch_bounds__(256, 2) gemm_mma_kernel(
    const float* __restrict__ A, const float* __restrict__ Bm,
    const float* __restrict__ al, const float* __restrict__ ar, int nRows) {
    extern __shared__ float sm[];
    int tid = threadIdx.x;
    int wid = tid >> 5;
    int lane = tid & 31;
    int gid = lane >> 2;      // 0..7
    int tig = lane & 3;       // 0..3
    int warp_m = wid & 1;     // 0..1 (32 rows each)
    int warp_n = wid >> 1;    // 0..3 (32 cols each == one head)
    int rowBase = blockIdx.x * 64;

    float c[2][4][4];
    #pragma unroll
    for (int mt = 0; mt < 2; mt++)
        #pragma unroll
        for (int nt = 0; nt < 4; nt++)
            #pragma unroll
            for (int j = 0; j < 4; j++) c[mt][nt][j] = 0.f;

    for (int ch = 0; ch < 8; ch++) {
        int k0 = ch * 32;
        __syncthreads();
        #pragma unroll
        for (int i = 0; i < 2; i++) {
            int f = i * 256 + tid;
            int r = f >> 3, kq = f & 7;
            int gr = rowBase + r;
            float4 v = make_float4(0.f, 0.f, 0.f, 0.f);
            if (gr < nRows) v = *(const float4*)(A + (size_t)gr * KIN + k0 + kq * 4);
            float* ph = sm + AS_HI + r * A_STRIDE + kq * 4;
            float* pl = sm + AS_LO + r * A_STRIDE + kq * 4;
            float h0 = tf32_rna(v.x), h1 = tf32_rna(v.y), h2 = tf32_rna(v.z), h3 = tf32_rna(v.w);
            ph[0] = h0; ph[1] = h1; ph[2] = h2; ph[3] = h3;
            pl[0] = tf32_rna(v.x - h0); pl[1] = tf32_rna(v.y - h1);
            pl[2] = tf32_rna(v.z - h2); pl[3] = tf32_rna(v.w - h3);
        }
        #pragma unroll
        for (int i = 0; i < 4; i++) {
            int f = i * 256 + tid;
            int r = f >> 5, cq = f & 31;
            float4 v = *(const float4*)(Bm + (size_t)(k0 + r) * HO + cq * 4);
            float* ph = sm + BS_HI + r * B_STRIDE + cq * 4;
            float* pl = sm + BS_LO + r * B_STRIDE + cq * 4;
            float h0 = tf32_rna(v.x), h1 = tf32_rna(v.y), h2 = tf32_rna(v.z), h3 = tf32_rna(v.w);
            ph[0] = h0; ph[1] = h1; ph[2] = h2; ph[3] = h3;
            pl[0] = tf32_rna(v.x - h0); pl[1] = tf32_rna(v.y - h1);
            pl[2] = tf32_rna(v.z - h2); pl[3] = tf32_rna(v.w - h3);
        }
        __syncthreads();

        #pragma unroll
        for (int ks = 0; ks < 4; ks++) {
            int kb = ks * 8;
            uint32_t ah[2][4], alo[2][4], bh[4][2], blo[4][2];
            #pragma unroll
            for (int mt = 0; mt < 2; mt++) {
                int ra = warp_m * 32 + mt * 16 + gid;
                const float* ph = sm + AS_HI + ra * A_STRIDE + kb + tig;
                const float* pl = sm + AS_LO + ra * A_STRIDE + kb + tig;
                ah[mt][0] = __float_as_uint(ph[0]);
                ah[mt][1] = __float_as_uint(ph[8 * A_STRIDE]);
                ah[mt][2] = __float_as_uint(ph[4]);
                ah[mt][3] = __float_as_uint(ph[8 * A_STRIDE + 4]);
                alo[mt][0] = __float_as_uint(pl[0]);
                alo[mt][1] = __float_as_uint(pl[8 * A_STRIDE]);
                alo[mt][2] = __float_as_uint(pl[4]);
                alo[mt][3] = __float_as_uint(pl[8 * A_STRIDE + 4]);
            }
            #pragma unroll
            for (int nt = 0; nt < 4; nt++) {
                int cb = warp_n * 32 + nt * 8 + gid;
                const float* ph = sm + BS_HI + (kb + tig) * B_STRIDE + cb;
                const float* pl = sm + BS_LO + (kb + tig) * B_STRIDE + cb;
                bh[nt][0] = __float_as_uint(ph[0]);
                bh[nt][1] = __float_as_uint(ph[4 * B_STRIDE]);
                blo[nt][0] = __float_as_uint(pl[0]);
                blo[nt][1] = __float_as_uint(pl[4 * B_STRIDE]);
            }
            #pragma unroll
            for (int mt = 0; mt < 2; mt++)
                #pragma unroll
                for (int nt = 0; nt < 4; nt++) {
                    mma_tf32(c[mt][nt][0], c[mt][nt][1], c[mt][nt][2], c[mt][nt][3],
                             ah[mt][0], ah[mt][1], ah[mt][2], ah[mt][3], bh[nt][0], bh[nt][1]);
                    mma_tf32(c[mt][nt][0], c[mt][nt][1], c[mt][nt][2], c[mt][nt][3],
                             alo[mt][0], alo[mt][1], alo[mt][2], alo[mt][3], bh[nt][0], bh[nt][1]);
                    mma_tf32(c[mt][nt][0], c[mt][nt][1], c[mt][nt][2], c[mt][nt][3],
                             ah[mt][0], ah[mt][1], ah[mt][2], ah[mt][3], blo[nt][0], blo[nt][1]);
                }
        }
    }

    // Epilogue: store feat + fused el/er.
    float alv[4][2], arv[4][2];
    #pragma unroll
    for (int nt = 0; nt < 4; nt++) {
        int col = warp_n * 32 + nt * 8 + 2 * tig;
        alv[nt][0] = al[col]; alv[nt][1] = al[col + 1];
        arv[nt][0] = ar[col]; arv[nt][1] = ar[col + 1];
    }
    #pragma unroll
    for (int mt = 0; mt < 2; mt++) {
        #pragma unroll
        for (int half = 0; half < 2; half++) {
            int row = warp_m * 32 + mt * 16 + gid + half * 8;
            int node = rowBase + row;
            bool ok = (node < nRows);
            float el = 0.f, er = 0.f;
            #pragma unroll
            for (int nt = 0; nt < 4; nt++) {
                float v0 = c[mt][nt][half * 2 + 0];
                float v1 = c[mt][nt][half * 2 + 1];
                if (ok) {
                    int col = warp_n * 32 + nt * 8 + 2 * tig;
                    *(float2*)(g_feat + (size_t)node * HO + col) = make_float2(v0, v1);
                }
                el = fmaf(v0, alv[nt][0], el); el = fmaf(v1, alv[nt][1], el);
                er = fmaf(v0, arv[nt][0], er); er = fmaf(v1, arv[nt][1], er);
            }
            el += __shfl_down_sync(0xffffffffu, el, 2, 4);
            el += __shfl_down_sync(0xffffffffu, el, 1, 4);
            er += __shfl_down_sync(0xffffffffu, er, 2, 4);
            er += __shfl_down_sync(0xffffffffu, er, 1, 4);
            if (ok && tig == 0) {
                g_el[node * HEADS + warp_n] = el;
                g_er[node * HEADS + warp_n] = er;
            }
        }
    }
}

// ---------------- edge logits: V in registers, grid-stride ----------------
// 8 lanes per edge, 4 edges per warp per iteration. Lane r holds V rows
// r*8..r*8+7 (all 4 heads) in registers -> zero shared traffic in the loop.
__global__ void __launch_bounds__(256) edge_logits_kernel(
    const float* __restrict__ ef, const int* __restrict__ src,
    const int* __restrict__ dst, int E) {
    int lane = threadIdx.x & 31;
    int r = lane & 7;
    int grp = lane >> 3;
    int gwarp = (blockIdx.x * blockDim.x + threadIdx.x) >> 5;
    int nwarp = (gridDim.x * blockDim.x) >> 5;

    // preload V rows r*8..r*8+7 into registers: vr[i] = V[r*8+i][0..3]
    float4 vr[8];
    #pragma unroll
    for (int i = 0; i < 8; i++)
        vr[i] = *(const float4*)(g_V + (r * 8 + i) * HEADS);

    for (int e0 = gwarp * 4; e0 < E; e0 += nwarp * 4) {
        int e = e0 + grp;
        float acc0 = 0.f, acc1 = 0.f, acc2 = 0.f, acc3 = 0.f;
        if (e < E) {
            const float4* p = (const float4*)(ef + (size_t)e * 64 + r * 8);
            float4 x0 = p[0], x1 = p[1];
            float v[8] = {x0.x, x0.y, x0.z, x0.w, x1.x, x1.y, x1.z, x1.w};
            #pragma unroll
            for (int i = 0; i < 8; i++) {
                acc0 = fmaf(v[i], vr[i].x, acc0);
                acc1 = fmaf(v[i], vr[i].y, acc1);
                acc2 = fmaf(v[i], vr[i].z, acc2);
                acc3 = fmaf(v[i], vr[i].w, acc3);
            }
        }
        #pragma unroll
        for (int off = 4; off >= 1; off >>= 1) {
            acc0 += __shfl_down_sync(0xffffffffu, acc0, off, 8);
            acc1 += __shfl_down_sync(0xffffffffu, acc1, off, 8);
            acc2 += __shfl_down_sync(0xffffffffu, acc2, off, 8);
            acc3 += __shfl_down_sync(0xffffffffu, acc3, off, 8);
        }
        if (r == 0 && e < E) {
            int s = src[e], d = dst[e];
            float4 el4 = *(const float4*)(g_el + s * HEADS);
            float4 er4 = *(const float4*)(g_er + d * HEADS);
            float l[HEADS];
            l[0] = acc0 + el4.x + er4.x;
            l[1] = acc1 + el4.y + er4.y;
            l[2] = acc2 + el4.z + er4.z;
            l[3] = acc3 + el4.w + er4.w;
            #pragma unroll
            for (int h = 0; h < HEADS; h++)
                l[h] = (l[h] >= 0.f) ? l[h] : NEG_SLOPE * l[h];
            *(float4*)(g_logit + (size_t)e * HEADS) = make_float4(l[0], l[1], l[2], l[3]);
            #pragma unroll
            for (int h = 0; h < HEADS; h++)
                atomicMax(&g_mx[d * HEADS + h], fenc(l[h]));
            atomicAdd(&g_cnt[d], 1);
        }
    }
}

// ---------------- scans ----------------
__global__ void scan1_kernel(int n) {
    __shared__ int s[1024];
    int tid = threadIdx.x;
    int i = blockIdx.x * 1024 + tid;
    int v = (i < n) ? g_cnt[i] : 0;
    s[tid] = v;
    __syncthreads();
    #pragma unroll
    for (int off = 1; off < 1024; off <<= 1) {
        int t = (tid >= off) ? s[tid - off] : 0;
        __syncthreads();
        s[tid] += t;
        __syncthreads();
    }
    if (i < n) g_rowptr[i] = s[tid] - v;
    if (tid == 1023) g_part[blockIdx.x] = s[1023];
}
__global__ void scan2_kernel(int nblocks) {
    __shared__ int s[64];
    int tid = threadIdx.x;
    int v = (tid < nblocks) ? g_part[tid] : 0;
    s[tid] = v;
    __syncthreads();
    #pragma unroll
    for (int off = 1; off < 64; off <<= 1) {
        int t = (tid >= off) ? s[tid - off] : 0;
        __syncthreads();
        s[tid] += t;
        __syncthreads();
    }
    g_partx[tid] = s[tid] - v;
}
__global__ void scan3_kernel(int n, int E) {
    int i = blockIdx.x * blockDim.x + threadIdx.x;
    if (i < n) g_rowptr[i] += g_partx[i >> 10];
    if (i == 0) g_rowptr[n] = E;
}

// ---------------- scatter: build packed CSR (src, exp4) ----------------
__global__ void scatter_kernel(const int* __restrict__ src, const int* __restrict__ dst, int E) {
    int e = blockIdx.x * blockDim.x + threadIdx.x;
    if (e >= E) return;
    int d = dst[e];
    float4 lg = *(const float4*)(g_logit + (size_t)e * HEADS);
    const unsigned* mp = &g_mx[d * HEADS];
    float4 ev;
    ev.x = expf(lg.x - fdec(mp[0]));
    ev.y = expf(lg.y - fdec(mp[1]));
    ev.z = expf(lg.z - fdec(mp[2]));
    ev.w = expf(lg.w - fdec(mp[3]));
    int pos = g_rowptr[d] + atomicAdd(&g_cursor[d], 1);
    g_esrc[pos] = src[e];
    g_eexp[pos] = ev;
}

// ---------------- aggregation: warp per dst node, denom inline ----------------
__global__ void aggregate_kernel(float* __restrict__ out, int N) {
    int warp = (blockIdx.x * blockDim.x + threadIdx.x) >> 5;
    int lane = threadIdx.x & 31;
    if (warp >= N) return;
    int h = lane >> 3;
    int beg = g_rowptr[warp], end = g_rowptr[warp + 1];
    const float* ge = (const float*)g_eexp;
    float denom = 0.f;
    float4 acc = make_float4(0.f, 0.f, 0.f, 0.f);
    int s_next = 0;
    float a_next = 0.f;
    if (beg < end) { s_next = g_esrc[beg]; a_next = ge[(size_t)beg * 4 + h]; }
    for (int j = beg; j < end; j++) {
        int s = s_next;
        float a = a_next;
        if (j + 1 < end) { s_next = g_esrc[j + 1]; a_next = ge[(size_t)(j + 1) * 4 + h]; }
        float4 f = *(const float4*)(g_feat + (size_t)s * HO + lane * 4);
        acc.x = fmaf(a, f.x, acc.x);
        acc.y = fmaf(a, f.y, acc.y);
        acc.z = fmaf(a, f.z, acc.z);
        acc.w = fmaf(a, f.w, acc.w);
        denom += a;
    }
    float4 res = make_float4(0.f, 0.f, 0.f, 0.f);
    if (end > beg) {
        float inv = 1.f / denom;
        res.x = fmaxf(acc.x * inv, 0.f);
        res.y = fmaxf(acc.y * inv, 0.f);
        res.z = fmaxf(acc.z * inv, 0.f);
        res.w = fmaxf(acc.w * inv, 0.f);
    }
    *(float4*)(out + (size_t)warp * HO + lane * 4) = res;
}

// ---------------- launch ----------------
extern "C" void kernel_launch(void* const* d_in, const int* in_sizes, int n_in,
                              void* d_out, int out_size) {
    const float* node_feat = (const float*)d_in[0];
    const float* edge_feat = (const float*)d_in[1];
    const float* W         = (const float*)d_in[2];
    const float* W_e       = (const float*)d_in[3];
    const float* attn_l    = (const float*)d_in[4];
    const float* attn_r    = (const float*)d_in[5];
    const float* attn_e    = (const float*)d_in[6];
    const int*   src       = (const int*)d_in[7];
    const int*   dst       = (const int*)d_in[8];
    float* out = (float*)d_out;

    int N = in_sizes[0] / KIN;
    int E = in_sizes[7];

    cudaFuncSetAttribute(gemm_mma_kernel,
                         cudaFuncAttributeMaxDynamicSharedMemorySize, GEMM_SMEM);

    init_kernel<<<(N * HEADS + 255) / 256, 256>>>();
    vprep_kernel<<<1, 256>>>(W_e, attn_e);
    gemm_mma_kernel<<<(N + 63) / 64, 256, GEMM_SMEM>>>(node_feat, W, attn_l, attn_r, N);
    edge_logits_kernel<<<1184, 256>>>(edge_feat, src, dst, E);
    int nScanBlocks = (N + 1023) / 1024;
    scan1_kernel<<<nScanBlocks, 1024>>>(N);
    scan2_kernel<<<1, 64>>>(nScanBlocks);
    scan3_kernel<<<(N + 255) / 256, 256>>>(N, E);
    scatter_kernel<<<(E + 255) / 256, 256>>>(src, dst, E);
    aggregate_kernel<<<(N + 7) / 8, 256>>>(out, N);
}